// round 12
// baseline (speedup 1.0000x reference)
#include <cuda_runtime.h>
#include <cuda_bf16.h>
#include <cstdint>

#define N_TOKENS 8192
#define D_MODEL  4096
#define N_EXPERTS 256
#define N_GROUP 4
#define GROUP_SIZE 64
#define TOPK_TOTAL 8

#define BM 64
#define BN 128
#define BK 64
#define NCHUNK (D_MODEL / BK)   // 64
#define THREADS 256             // 4 consumer + 4 producer warps

// stage layout (bytes): Ahi[64*128] Alo Bhi[128*128] Blo
#define AHI 0
#define ALO 8192
#define BHI 16384
#define BLO 32768
#define STAGE_BYTES 49152
#define STAGE_OFF 1024
#define SMEM_TOTAL (STAGE_OFF + 2 * STAGE_BYTES)   // 99328 -> 2 CTAs/SM

// pre-split W (bf16 hi/lo)
__device__ __nv_bfloat16 g_whi[N_EXPERTS * D_MODEL];
__device__ __nv_bfloat16 g_wlo[N_EXPERTS * D_MODEL];

__device__ __forceinline__ uint32_t smem_u32(const void* p) {
    uint32_t a;
    asm("{ .reg .u64 t; cvta.to.shared.u64 t, %1; cvt.u32.u64 %0, t; }" : "=r"(a) : "l"(p));
    return a;
}
__device__ __forceinline__ void mbar_init(uint32_t m, uint32_t cnt) {
    asm volatile("mbarrier.init.shared.b64 [%0], %1;" :: "r"(m), "r"(cnt) : "memory");
}
__device__ __forceinline__ void mbar_wait(uint32_t m, int parity) {
    asm volatile(
        "{\n\t.reg .pred P;\n\t"
        "WL_%=:\n\t"
        "mbarrier.try_wait.parity.acquire.cta.shared::cta.b64 P, [%0], %1;\n\t"
        "@!P bra WL_%=;\n\t}"
        :: "r"(m), "r"(parity) : "memory");
}
__device__ __forceinline__ void mbar_arrive(uint32_t m) {
    asm volatile("mbarrier.arrive.shared.b64 _, [%0];" :: "r"(m) : "memory");
}
__device__ __forceinline__ void cpasync_mbar_arrive(uint32_t m) {
    asm volatile("cp.async.mbarrier.arrive.noinc.shared.b64 [%0];" :: "r"(m) : "memory");
}
__device__ __forceinline__ void cp16(uint32_t dst, const void* src) {
    asm volatile("cp.async.cg.shared.global [%0], [%1], 16;" :: "r"(dst), "l"(src) : "memory");
}
__device__ __forceinline__ void ldsm4(uint32_t (&r)[4], uint32_t addr) {
    asm volatile("ldmatrix.sync.aligned.m8n8.x4.shared.b16 {%0,%1,%2,%3}, [%4];"
                 : "=r"(r[0]), "=r"(r[1]), "=r"(r[2]), "=r"(r[3]) : "r"(addr));
}
__device__ __forceinline__ void mma16816(float (&c)[4], const uint32_t (&a)[4],
                                         uint32_t b0, uint32_t b1) {
    asm volatile("mma.sync.aligned.m16n8k16.row.col.f32.bf16.bf16.f32 "
                 "{%0,%1,%2,%3}, {%4,%5,%6,%7}, {%8,%9}, {%0,%1,%2,%3};"
                 : "+f"(c[0]), "+f"(c[1]), "+f"(c[2]), "+f"(c[3])
                 : "r"(a[0]), "r"(a[1]), "r"(a[2]), "r"(a[3]), "r"(b0), "r"(b1));
}
__device__ __forceinline__ void pack_hilo(float x, float y, uint32_t& hi, uint32_t& lo) {
    asm("cvt.rn.bf16x2.f32 %0, %1, %2;" : "=r"(hi) : "f"(y), "f"(x));
    float hx = __uint_as_float(hi << 16);
    float hy = __uint_as_float(hi & 0xFFFF0000u);
    asm("cvt.rn.bf16x2.f32 %0, %1, %2;" : "=r"(lo) : "f"(y - hy), "f"(x - hx));
}

// ---- kernel 0: split W fp32 -> bf16 hi/lo ----
__global__ __launch_bounds__(256) void split_w_kernel(const float* __restrict__ W) {
    size_t i = ((size_t)blockIdx.x * 256 + threadIdx.x) * 4;
    float4 v = *(const float4*)(W + i);
    uint2 hi, lo;
    pack_hilo(v.x, v.y, hi.x, lo.x);
    pack_hilo(v.z, v.w, hi.y, lo.y);
    *(uint2*)(g_whi + i) = hi;
    *(uint2*)(g_wlo + i) = lo;
}

// ---- kernel 1: warp-specialized GEMM, 32x64 consumer warp tiles, 2 CTAs/SM ----
__global__ __launch_bounds__(THREADS, 2) void moe_gemm_kernel(
    const float* __restrict__ H,
    float* __restrict__ out_logits)
{
    extern __shared__ char smem[];
    const uint32_t sb = smem_u32(smem);
    const int tid  = threadIdx.x;
    const int wid  = tid >> 5;
    const int lane = tid & 31;
    const int bm   = (blockIdx.x >> 1) * BM;
    const int bn   = (blockIdx.x & 1) * BN;

    // full0@0 full1@8 (256: 128 STS arrives + 128 cp.async arrives)
    // empty0@16 empty1@24 (128 consumer threads)
    if (tid == 0) {
        mbar_init(sb + 0, 256);  mbar_init(sb + 8, 256);
        mbar_init(sb + 16, 128); mbar_init(sb + 24, 128);
    }
    __syncthreads();

    if (wid < 4) {
        // ============ CONSUMER: warp tile 32 x 64 ============
        const int mset = (wid & 1) * 32;
        const int ng   = (wid >> 1) * 64;
        int ph[2] = {0, 0};

        float acc[2][8][4];
#pragma unroll
        for (int a = 0; a < 2; a++)
#pragma unroll
            for (int b = 0; b < 8; b++)
#pragma unroll
                for (int c = 0; c < 4; c++) acc[a][b][c] = 0.f;

        for (int c = 0; c < NCHUNK; c++) {
            const int s = c & 1;
            mbar_wait(sb + s * 8, ph[s]); ph[s] ^= 1;
            const uint32_t stg = sb + STAGE_OFF + s * STAGE_BYTES;
#pragma unroll
            for (int k16 = 0; k16 < 4; k16++) {
                const uint32_t cb = (uint32_t)k16 * 32 + ((lane >> 4) << 4);
                uint32_t ah[2][4], al[2][4];
#pragma unroll
                for (int mt = 0; mt < 2; mt++) {
                    const int mrow = mset + mt * 16 + (lane & 15);
                    uint32_t a = stg + AHI + (uint32_t)mrow * 128
                               + (cb ^ ((uint32_t)(mrow & 7) << 4));
                    ldsm4(ah[mt], a);
                    ldsm4(al[mt], a + (ALO - AHI));
                }
#pragma unroll
                for (int n16 = 0; n16 < 4; n16++) {
                    const int nrow = ng + n16 * 16 + (lane & 15);
                    uint32_t b = stg + BHI + (uint32_t)nrow * 128
                               + (cb ^ ((uint32_t)(nrow & 7) << 4));
                    uint32_t bh[4], bl[4];
                    ldsm4(bh, b);
                    ldsm4(bl, b + (BLO - BHI));
#pragma unroll
                    for (int mt = 0; mt < 2; mt++) {
                        mma16816(acc[mt][n16 * 2 + 0], ah[mt], bh[0], bh[2]);
                        mma16816(acc[mt][n16 * 2 + 1], ah[mt], bh[1], bh[3]);
                    }
#pragma unroll
                    for (int mt = 0; mt < 2; mt++) {
                        mma16816(acc[mt][n16 * 2 + 0], ah[mt], bl[0], bl[2]);
                        mma16816(acc[mt][n16 * 2 + 1], ah[mt], bl[1], bl[3]);
                    }
#pragma unroll
                    for (int mt = 0; mt < 2; mt++) {
                        mma16816(acc[mt][n16 * 2 + 0], al[mt], bh[0], bh[2]);
                        mma16816(acc[mt][n16 * 2 + 1], al[mt], bh[1], bh[3]);
                    }
                }
            }
            mbar_arrive(sb + 16 + s * 8);
        }

        // epilogue: write logits straight from registers
        const int cl0 = 2 * (lane & 3);
#pragma unroll
        for (int mt = 0; mt < 2; mt++) {
            const int m0 = mset + mt * 16 + (lane >> 2);
#pragma unroll
            for (int nf = 0; nf < 8; nf++) {
                const int col = bn + ng + nf * 8 + cl0;
                *(float2*)&out_logits[(size_t)(bm + m0) * N_EXPERTS + col] =
                    make_float2(acc[mt][nf][0], acc[mt][nf][1]);
                *(float2*)&out_logits[(size_t)(bm + m0 + 8) * N_EXPERTS + col] =
                    make_float2(acc[mt][nf][2], acc[mt][nf][3]);
            }
        }
    } else {
        // ============ PRODUCER ============
        const int pt = tid - 128;                 // 0..127
        const int arow = pt >> 1;                 // 0..63
        const int acol = (pt & 1) * 32;           // float index, 32 floats each
        const uint32_t axor = (uint32_t)(arow & 7) << 4;
        const float* hp = H + (size_t)(bm + arow) * D_MODEL + acol;
        const int brow = pt;                      // 0..127, one 128B row each
        const uint32_t bxor = (uint32_t)(brow & 7) << 4;
        const __nv_bfloat16* whp = g_whi + (size_t)(bn + brow) * D_MODEL;
        const __nv_bfloat16* wlp = g_wlo + (size_t)(bn + brow) * D_MODEL;
        int ph[2] = {0, 0};

        float4 ha[8];
#pragma unroll
        for (int j = 0; j < 8; j++) ha[j] = *(const float4*)(hp + j * 4);

        for (int c = 0; c < NCHUNK; c++) {
            const int s = c & 1;
            if (c >= 2) { mbar_wait(sb + 16 + s * 8, ph[s]); ph[s] ^= 1; }
            char* stage = smem + STAGE_OFF + s * STAGE_BYTES;
            const uint32_t stg = sb + STAGE_OFF + s * STAGE_BYTES;

            // A convert + STS (32 floats)
#pragma unroll
            for (int j = 0; j < 8; j++) {
                uint32_t off = (uint32_t)arow * 128
                             + (((uint32_t)(acol + j * 4) * 2) ^ axor);
                uint2 hi, lo;
                pack_hilo(ha[j].x, ha[j].y, hi.x, lo.x);
                pack_hilo(ha[j].z, ha[j].w, hi.y, lo.y);
                *(uint2*)(stage + AHI + off) = hi;
                *(uint2*)(stage + ALO + off) = lo;
            }
            mbar_arrive(sb + s * 8);

            // B via cp.async: one full 128B hi row + lo row per thread
            const uint32_t bd = stg + BHI + (uint32_t)brow * 128;
#pragma unroll
            for (int j = 0; j < 8; j++) {
                uint32_t sw = ((uint32_t)j * 16) ^ bxor;
                cp16(bd + sw, whp + c * BK + j * 8);
                cp16(bd + (BLO - BHI) + sw, wlp + c * BK + j * 8);
            }
            cpasync_mbar_arrive(sb + s * 8);

            // prefetch next A while cp.asyncs fly
            if (c + 1 < NCHUNK) {
                const float* hn = hp + (c + 1) * BK;
#pragma unroll
                for (int j = 0; j < 8; j++) ha[j] = *(const float4*)(hn + j * 4);
            }
        }
    }
}

// ---- kernel 2: topk (one warp per token) ----
__global__ __launch_bounds__(256) void moe_topk_kernel(
    const float* __restrict__ logits,
    float* __restrict__ out_idx,
    float* __restrict__ out_w)
{
    __shared__ float sc[8][N_EXPERTS];
    __shared__ float bval[8][TOPK_TOTAL];
    __shared__ int   bidx[8][TOPK_TOTAL];

    const int warp = threadIdx.x >> 5;
    const int lane = threadIdx.x & 31;
    const int t = blockIdx.x * 8 + warp;

    const float* lg = logits + (size_t)t * N_EXPERTS;
#pragma unroll
    for (int i = 0; i < N_EXPERTS / 32; i++) {
        float x = lg[lane + i * 32];
        sc[warp][lane + i * 32] = 1.f / (1.f + __expf(-x));
    }
    __syncwarp();

    if (lane < N_GROUP) {
        const int g = lane;
        float b1 = -1.f, b2 = -1.f;
        int i1 = 0, i2 = 0;
#pragma unroll 4
        for (int j = 0; j < GROUP_SIZE; j++) {
            float s = sc[warp][g * GROUP_SIZE + j];
            if (s > b1) { b2 = b1; i2 = i1; b1 = s; i1 = j; }
            else if (s > b2) { b2 = s; i2 = j; }
        }
        bval[warp][g * 2]     = b1; bidx[warp][g * 2]     = g * GROUP_SIZE + i1;
        bval[warp][g * 2 + 1] = b2; bidx[warp][g * 2 + 1] = g * GROUP_SIZE + i2;
    }
    __syncwarp();

    if (lane == 0) {
        float sum = 0.f;
#pragma unroll
        for (int j = 0; j < TOPK_TOTAL; j++) sum += bval[warp][j];
        float scale = 2.5f / (sum + 1e-10f);
#pragma unroll
        for (int j = 0; j < TOPK_TOTAL; j++) {
            out_idx[(size_t)t * TOPK_TOTAL + j] = (float)bidx[warp][j];
            out_w[(size_t)t * TOPK_TOTAL + j]   = bval[warp][j] * scale;
        }
    }
}

extern "C" void kernel_launch(void* const* d_in, const int* in_sizes, int n_in,
                              void* d_out, int out_size)
{
    const float* H = (const float*)d_in[0];   // [8192, 4096]
    const float* W = (const float*)d_in[1];   // [256, 4096]
    float* out = (float*)d_out;

    float* out_idx    = out;
    float* out_w      = out + (size_t)N_TOKENS * TOPK_TOTAL;
    float* out_logits = out + (size_t)N_TOKENS * TOPK_TOTAL * 2;

    static int configured = 0;
    if (!configured) {
        cudaFuncSetAttribute(moe_gemm_kernel,
                             cudaFuncAttributeMaxDynamicSharedMemorySize, SMEM_TOTAL);
        configured = 1;
    }
    split_w_kernel<<<(N_EXPERTS * D_MODEL / 4) / 256, 256>>>(W);
    moe_gemm_kernel<<<(N_TOKENS / BM) * (N_EXPERTS / BN), THREADS, SMEM_TOTAL>>>(H, out_logits);
    moe_topk_kernel<<<N_TOKENS / 8, 256>>>(out_logits, out_idx, out_w);
}

// round 13
// speedup vs baseline: 1.2454x; 1.2454x over previous
#include <cuda_runtime.h>
#include <cuda_bf16.h>
#include <cstdint>

#define N_TOKENS 8192
#define D_MODEL  4096
#define N_EXPERTS 256
#define N_GROUP 4
#define GROUP_SIZE 64
#define TOPK_TOTAL 8

#define BM 64
#define BN 128
#define BK 64
#define NCHUNK (D_MODEL / BK)   // 64
#define THREADS 512             // 8 consumer + 8 producer warps

// stage layout (bytes): Ahi[64*128] Alo Bhi[128*128] Blo
#define AHI 0
#define ALO 8192
#define BHI 16384
#define BLO 32768
#define STAGE_BYTES 49152
#define STAGE_OFF 1024
#define SMEM_TOTAL (STAGE_OFF + 2 * STAGE_BYTES)   // 99328 -> 2 CTAs/SM

// pre-split W (bf16 hi/lo)
__device__ __nv_bfloat16 g_whi[N_EXPERTS * D_MODEL];
__device__ __nv_bfloat16 g_wlo[N_EXPERTS * D_MODEL];

__device__ __forceinline__ uint32_t smem_u32(const void* p) {
    uint32_t a;
    asm("{ .reg .u64 t; cvta.to.shared.u64 t, %1; cvt.u32.u64 %0, t; }" : "=r"(a) : "l"(p));
    return a;
}
__device__ __forceinline__ void mbar_init(uint32_t m, uint32_t cnt) {
    asm volatile("mbarrier.init.shared.b64 [%0], %1;" :: "r"(m), "r"(cnt) : "memory");
}
__device__ __forceinline__ void mbar_wait(uint32_t m, int parity) {
    asm volatile(
        "{\n\t.reg .pred P;\n\t"
        "WL_%=:\n\t"
        "mbarrier.try_wait.parity.acquire.cta.shared::cta.b64 P, [%0], %1;\n\t"
        "@!P bra WL_%=;\n\t}"
        :: "r"(m), "r"(parity) : "memory");
}
__device__ __forceinline__ void mbar_arrive(uint32_t m) {
    asm volatile("mbarrier.arrive.shared.b64 _, [%0];" :: "r"(m) : "memory");
}
__device__ __forceinline__ void cpasync_mbar_arrive(uint32_t m) {
    asm volatile("cp.async.mbarrier.arrive.noinc.shared.b64 [%0];" :: "r"(m) : "memory");
}
__device__ __forceinline__ void cp16(uint32_t dst, const void* src) {
    asm volatile("cp.async.cg.shared.global [%0], [%1], 16;" :: "r"(dst), "l"(src) : "memory");
}
__device__ __forceinline__ void ldsm4(uint32_t (&r)[4], uint32_t addr) {
    asm volatile("ldmatrix.sync.aligned.m8n8.x4.shared.b16 {%0,%1,%2,%3}, [%4];"
                 : "=r"(r[0]), "=r"(r[1]), "=r"(r[2]), "=r"(r[3]) : "r"(addr));
}
__device__ __forceinline__ void mma16816(float (&c)[4], const uint32_t (&a)[4],
                                         uint32_t b0, uint32_t b1) {
    asm volatile("mma.sync.aligned.m16n8k16.row.col.f32.bf16.bf16.f32 "
                 "{%0,%1,%2,%3}, {%4,%5,%6,%7}, {%8,%9}, {%0,%1,%2,%3};"
                 : "+f"(c[0]), "+f"(c[1]), "+f"(c[2]), "+f"(c[3])
                 : "r"(a[0]), "r"(a[1]), "r"(a[2]), "r"(a[3]), "r"(b0), "r"(b1));
}
__device__ __forceinline__ void pack_hilo(float x, float y, uint32_t& hi, uint32_t& lo) {
    asm("cvt.rn.bf16x2.f32 %0, %1, %2;" : "=r"(hi) : "f"(y), "f"(x));
    float hx = __uint_as_float(hi << 16);
    float hy = __uint_as_float(hi & 0xFFFF0000u);
    asm("cvt.rn.bf16x2.f32 %0, %1, %2;" : "=r"(lo) : "f"(y - hy), "f"(x - hx));
}

// ---- kernel 0: split W fp32 -> bf16 hi/lo ----
__global__ __launch_bounds__(256) void split_w_kernel(const float* __restrict__ W) {
    size_t i = ((size_t)blockIdx.x * 256 + threadIdx.x) * 4;
    float4 v = *(const float4*)(W + i);
    uint2 hi, lo;
    pack_hilo(v.x, v.y, hi.x, lo.x);
    pack_hilo(v.z, v.w, hi.y, lo.y);
    *(uint2*)(g_whi + i) = hi;
    *(uint2*)(g_wlo + i) = lo;
}

// ---- kernel 1: warp-specialized GEMM, 16x64 consumer warp tiles, 2 CTAs/SM ----
__global__ __launch_bounds__(THREADS, 2) void moe_gemm_kernel(
    const float* __restrict__ H,
    float* __restrict__ out_logits)
{
    extern __shared__ char smem[];
    const uint32_t sb = smem_u32(smem);
    const int tid  = threadIdx.x;
    const int wid  = tid >> 5;
    const int lane = tid & 31;
    const int bm   = (blockIdx.x >> 1) * BM;
    const int bn   = (blockIdx.x & 1) * BN;

    // full0@0 full1@8 (512: 256 STS arrives + 256 cp.async arrives)
    // empty0@16 empty1@24 (256 consumer threads)
    if (tid == 0) {
        mbar_init(sb + 0, 512);  mbar_init(sb + 8, 512);
        mbar_init(sb + 16, 256); mbar_init(sb + 24, 256);
    }
    __syncthreads();

    if (wid < 8) {
        // ============ CONSUMER: warp tile 16 x 64 ============
        const int mset = (wid & 3) * 16;
        const int ng   = (wid >> 2) * 64;
        int ph[2] = {0, 0};

        float acc[8][4];
#pragma unroll
        for (int b = 0; b < 8; b++)
#pragma unroll
            for (int c = 0; c < 4; c++) acc[b][c] = 0.f;

        const int mrow = mset + (lane & 15);
        const uint32_t a_xor = (uint32_t)(mrow & 7) << 4;
        // per-n16 row/addr components (lane-dependent, loop-invariant)
        const int nrl = lane & 15;

        for (int c = 0; c < NCHUNK; c++) {
            const int s = c & 1;
            mbar_wait(sb + s * 8, ph[s]); ph[s] ^= 1;
            const uint32_t stg = sb + STAGE_OFF + s * STAGE_BYTES;
#pragma unroll
            for (int k16 = 0; k16 < 4; k16++) {
                const uint32_t cb = (uint32_t)k16 * 32 + ((lane >> 4) << 4);

                // ---- batch ALL ldmatrix loads for this k16 (MLP=10) ----
                uint32_t ah[4], al[4], bh[4][4], bl[4][4];
                {
                    uint32_t a = stg + AHI + (uint32_t)mrow * 128 + (cb ^ a_xor);
                    ldsm4(ah, a);
                    ldsm4(al, a + (ALO - AHI));
                }
#pragma unroll
                for (int n16 = 0; n16 < 4; n16++) {
                    const int nrow = ng + n16 * 16 + nrl;
                    uint32_t b = stg + BHI + (uint32_t)nrow * 128
                               + (cb ^ ((uint32_t)(nrow & 7) << 4));
                    ldsm4(bh[n16], b);
                    ldsm4(bl[n16], b + (BLO - BHI));
                }

                // ---- term-major MMA order: same-acc RAW distance = 8 ----
#pragma unroll
                for (int n16 = 0; n16 < 4; n16++) {   // hi * hi
                    mma16816(acc[n16 * 2 + 0], ah, bh[n16][0], bh[n16][2]);
                    mma16816(acc[n16 * 2 + 1], ah, bh[n16][1], bh[n16][3]);
                }
#pragma unroll
                for (int n16 = 0; n16 < 4; n16++) {   // hi * lo
                    mma16816(acc[n16 * 2 + 0], ah, bl[n16][0], bl[n16][2]);
                    mma16816(acc[n16 * 2 + 1], ah, bl[n16][1], bl[n16][3]);
                }
#pragma unroll
                for (int n16 = 0; n16 < 4; n16++) {   // lo * hi
                    mma16816(acc[n16 * 2 + 0], al, bh[n16][0], bh[n16][2]);
                    mma16816(acc[n16 * 2 + 1], al, bh[n16][1], bh[n16][3]);
                }
            }
            mbar_arrive(sb + 16 + s * 8);
        }

        // epilogue: write logits straight from registers
        const int m0  = mset + (lane >> 2);
        const int cl0 = 2 * (lane & 3);
#pragma unroll
        for (int nf = 0; nf < 8; nf++) {
            const int col = bn + ng + nf * 8 + cl0;
            *(float2*)&out_logits[(size_t)(bm + m0) * N_EXPERTS + col] =
                make_float2(acc[nf][0], acc[nf][1]);
            *(float2*)&out_logits[(size_t)(bm + m0 + 8) * N_EXPERTS + col] =
                make_float2(acc[nf][2], acc[nf][3]);
        }
    } else {
        // ============ PRODUCER ============
        const int pt = tid - 256;                 // 0..255
        const int arow = pt >> 2;                 // 0..63
        const int acol = (pt & 3) * 16;
        const uint32_t axor = (uint32_t)(arow & 7) << 4;
        const float* hp = H + (size_t)(bm + arow) * D_MODEL + acol;
        const int brow  = pt >> 1;                // 0..127
        const int bhalf = (pt & 1) * 32;          // bf16 col offset
        const uint32_t bxor = (uint32_t)(brow & 7) << 4;
        const __nv_bfloat16* whp = g_whi + (size_t)(bn + brow) * D_MODEL + bhalf;
        const __nv_bfloat16* wlp = g_wlo + (size_t)(bn + brow) * D_MODEL + bhalf;
        int ph[2] = {0, 0};

        float4 ha[4];
#pragma unroll
        for (int j = 0; j < 4; j++) ha[j] = *(const float4*)(hp + j * 4);

        for (int c = 0; c < NCHUNK; c++) {
            const int s = c & 1;
            if (c >= 2) { mbar_wait(sb + 16 + s * 8, ph[s]); ph[s] ^= 1; }
            char* stage = smem + STAGE_OFF + s * STAGE_BYTES;
            const uint32_t stg = sb + STAGE_OFF + s * STAGE_BYTES;

            // A convert + STS
#pragma unroll
            for (int j = 0; j < 4; j++) {
                uint32_t off = (uint32_t)arow * 128
                             + (((uint32_t)(acol + j * 4) * 2) ^ axor);
                uint2 hi, lo;
                pack_hilo(ha[j].x, ha[j].y, hi.x, lo.x);
                pack_hilo(ha[j].z, ha[j].w, hi.y, lo.y);
                *(uint2*)(stage + AHI + off) = hi;
                *(uint2*)(stage + ALO + off) = lo;
            }
            mbar_arrive(sb + s * 8);

            // B via cp.async (pre-split bf16)
            const uint32_t bd = stg + BHI + (uint32_t)brow * 128;
#pragma unroll
            for (int j = 0; j < 4; j++) {
                uint32_t sw = (((uint32_t)(bhalf + j * 8) * 2) ^ bxor);
                cp16(bd + sw, whp + c * BK + j * 8);
                cp16(bd + (BLO - BHI) + sw, wlp + c * BK + j * 8);
            }
            cpasync_mbar_arrive(sb + s * 8);

            // prefetch next A while cp.asyncs fly
            if (c + 1 < NCHUNK) {
                const float* hn = hp + (c + 1) * BK;
#pragma unroll
                for (int j = 0; j < 4; j++) ha[j] = *(const float4*)(hn + j * 4);
            }
        }
    }
}

// ---- kernel 2: topk (one warp per token) ----
__global__ __launch_bounds__(256) void moe_topk_kernel(
    const float* __restrict__ logits,
    float* __restrict__ out_idx,
    float* __restrict__ out_w)
{
    __shared__ float sc[8][N_EXPERTS];
    __shared__ float bval[8][TOPK_TOTAL];
    __shared__ int   bidx[8][TOPK_TOTAL];

    const int warp = threadIdx.x >> 5;
    const int lane = threadIdx.x & 31;
    const int t = blockIdx.x * 8 + warp;

    const float* lg = logits + (size_t)t * N_EXPERTS;
#pragma unroll
    for (int i = 0; i < N_EXPERTS / 32; i++) {
        float x = lg[lane + i * 32];
        sc[warp][lane + i * 32] = 1.f / (1.f + __expf(-x));
    }
    __syncwarp();

    if (lane < N_GROUP) {
        const int g = lane;
        float b1 = -1.f, b2 = -1.f;
        int i1 = 0, i2 = 0;
#pragma unroll 4
        for (int j = 0; j < GROUP_SIZE; j++) {
            float s = sc[warp][g * GROUP_SIZE + j];
            if (s > b1) { b2 = b1; i2 = i1; b1 = s; i1 = j; }
            else if (s > b2) { b2 = s; i2 = j; }
        }
        bval[warp][g * 2]     = b1; bidx[warp][g * 2]     = g * GROUP_SIZE + i1;
        bval[warp][g * 2 + 1] = b2; bidx[warp][g * 2 + 1] = g * GROUP_SIZE + i2;
    }
    __syncwarp();

    if (lane == 0) {
        float sum = 0.f;
#pragma unroll
        for (int j = 0; j < TOPK_TOTAL; j++) sum += bval[warp][j];
        float scale = 2.5f / (sum + 1e-10f);
#pragma unroll
        for (int j = 0; j < TOPK_TOTAL; j++) {
            out_idx[(size_t)t * TOPK_TOTAL + j] = (float)bidx[warp][j];
            out_w[(size_t)t * TOPK_TOTAL + j]   = bval[warp][j] * scale;
        }
    }
}

extern "C" void kernel_launch(void* const* d_in, const int* in_sizes, int n_in,
                              void* d_out, int out_size)
{
    const float* H = (const float*)d_in[0];   // [8192, 4096]
    const float* W = (const float*)d_in[1];   // [256, 4096]
    float* out = (float*)d_out;

    float* out_idx    = out;
    float* out_w      = out + (size_t)N_TOKENS * TOPK_TOTAL;
    float* out_logits = out + (size_t)N_TOKENS * TOPK_TOTAL * 2;

    static int configured = 0;
    if (!configured) {
        cudaFuncSetAttribute(moe_gemm_kernel,
                             cudaFuncAttributeMaxDynamicSharedMemorySize, SMEM_TOTAL);
        configured = 1;
    }
    split_w_kernel<<<(N_EXPERTS * D_MODEL / 4) / 256, 256>>>(W);
    moe_gemm_kernel<<<(N_TOKENS / BM) * (N_EXPERTS / BN), THREADS, SMEM_TOTAL>>>(H, out_logits);
    moe_topk_kernel<<<N_TOKENS / 8, 256>>>(out_logits, out_idx, out_w);
}

// round 14
// speedup vs baseline: 1.4028x; 1.1264x over previous
#include <cuda_runtime.h>
#include <cuda_bf16.h>
#include <cstdint>

#define N_TOKENS 8192
#define D_MODEL  4096
#define N_EXPERTS 256
#define N_GROUP 4
#define GROUP_SIZE 64
#define TOPK_TOTAL 8

#define BM 128
#define BN 128
#define BK 64
#define NCHUNK (D_MODEL / BK)   // 64
#define THREADS 512             // 8 consumer + 8 producer warps
#define NSTAGE 3

// stage layout (bytes): Ahi[128*128] Alo Bhi[128*128] Blo
#define AHI 0
#define ALO 16384
#define BHI 32768
#define BLO 49152
#define STAGE_BYTES 65536
#define STAGE_OFF 1024
#define SMEM_TOTAL (STAGE_OFF + NSTAGE * STAGE_BYTES)   // 197632

// pre-split W (bf16 hi/lo)
__device__ __nv_bfloat16 g_whi[N_EXPERTS * D_MODEL];
__device__ __nv_bfloat16 g_wlo[N_EXPERTS * D_MODEL];

__device__ __forceinline__ uint32_t smem_u32(const void* p) {
    uint32_t a;
    asm("{ .reg .u64 t; cvta.to.shared.u64 t, %1; cvt.u32.u64 %0, t; }" : "=r"(a) : "l"(p));
    return a;
}
__device__ __forceinline__ void mbar_init(uint32_t m, uint32_t cnt) {
    asm volatile("mbarrier.init.shared.b64 [%0], %1;" :: "r"(m), "r"(cnt) : "memory");
}
__device__ __forceinline__ void mbar_wait(uint32_t m, int parity) {
    asm volatile(
        "{\n\t.reg .pred P;\n\t"
        "WL_%=:\n\t"
        "mbarrier.try_wait.parity.acquire.cta.shared::cta.b64 P, [%0], %1;\n\t"
        "@!P bra WL_%=;\n\t}"
        :: "r"(m), "r"(parity) : "memory");
}
__device__ __forceinline__ void mbar_arrive(uint32_t m) {
    asm volatile("mbarrier.arrive.shared.b64 _, [%0];" :: "r"(m) : "memory");
}
__device__ __forceinline__ void cpasync_mbar_arrive(uint32_t m) {
    asm volatile("cp.async.mbarrier.arrive.noinc.shared.b64 [%0];" :: "r"(m) : "memory");
}
__device__ __forceinline__ void cp16(uint32_t dst, const void* src) {
    asm volatile("cp.async.cg.shared.global [%0], [%1], 16;" :: "r"(dst), "l"(src) : "memory");
}
__device__ __forceinline__ void ldsm4(uint32_t (&r)[4], uint32_t addr) {
    asm volatile("ldmatrix.sync.aligned.m8n8.x4.shared.b16 {%0,%1,%2,%3}, [%4];"
                 : "=r"(r[0]), "=r"(r[1]), "=r"(r[2]), "=r"(r[3]) : "r"(addr));
}
__device__ __forceinline__ void mma16816(float (&c)[4], const uint32_t (&a)[4],
                                         uint32_t b0, uint32_t b1) {
    asm volatile("mma.sync.aligned.m16n8k16.row.col.f32.bf16.bf16.f32 "
                 "{%0,%1,%2,%3}, {%4,%5,%6,%7}, {%8,%9}, {%0,%1,%2,%3};"
                 : "+f"(c[0]), "+f"(c[1]), "+f"(c[2]), "+f"(c[3])
                 : "r"(a[0]), "r"(a[1]), "r"(a[2]), "r"(a[3]), "r"(b0), "r"(b1));
}
__device__ __forceinline__ void pack_hilo(float x, float y, uint32_t& hi, uint32_t& lo) {
    asm("cvt.rn.bf16x2.f32 %0, %1, %2;" : "=r"(hi) : "f"(y), "f"(x));
    float hx = __uint_as_float(hi << 16);
    float hy = __uint_as_float(hi & 0xFFFF0000u);
    asm("cvt.rn.bf16x2.f32 %0, %1, %2;" : "=r"(lo) : "f"(y - hy), "f"(x - hx));
}

// ---- kernel 0: split W fp32 -> bf16 hi/lo ----
__global__ __launch_bounds__(256) void split_w_kernel(const float* __restrict__ W) {
    size_t i = ((size_t)blockIdx.x * 256 + threadIdx.x) * 4;
    float4 v = *(const float4*)(W + i);
    uint2 hi, lo;
    pack_hilo(v.x, v.y, hi.x, lo.x);
    pack_hilo(v.z, v.w, hi.y, lo.y);
    *(uint2*)(g_whi + i) = hi;
    *(uint2*)(g_wlo + i) = lo;
}

// ---- kernel 1: warp-specialized GEMM, 32x64 warp tiles, 128x128 CTA tile ----
__global__ __launch_bounds__(THREADS, 1) void moe_gemm_kernel(
    const float* __restrict__ H,
    float* __restrict__ out_logits)
{
    extern __shared__ char smem[];
    const uint32_t sb = smem_u32(smem);
    const int tid  = threadIdx.x;
    const int wid  = tid >> 5;
    const int lane = tid & 31;
    const int bm   = (blockIdx.x >> 1) * BM;
    const int bn   = (blockIdx.x & 1) * BN;

    // full[s] at sb+s*8 (count 512: 256 STS + 256 cp.async arrives)
    // empty[s] at sb+24+s*8 (count 256 consumer threads)
    if (tid == 0) {
#pragma unroll
        for (int s = 0; s < NSTAGE; s++) {
            mbar_init(sb + s * 8, 512);
            mbar_init(sb + 24 + s * 8, 256);
        }
    }
    __syncthreads();

    if (wid < 8) {
        // ============ CONSUMER: warp tile 32 x 64 ============
        const int mset = (wid & 3) * 32;
        const int ng   = (wid >> 2) * 64;
        int ph[NSTAGE] = {0, 0, 0};
        int s = 0;

        float acc[2][8][4];
#pragma unroll
        for (int a = 0; a < 2; a++)
#pragma unroll
            for (int b = 0; b < 8; b++)
#pragma unroll
                for (int c = 0; c < 4; c++) acc[a][b][c] = 0.f;

        const int mrl = lane & 15;
        const int nrl = lane & 15;

        for (int c = 0; c < NCHUNK; c++) {
            mbar_wait(sb + s * 8, ph[s]); ph[s] ^= 1;
            const uint32_t stg = sb + STAGE_OFF + s * STAGE_BYTES;
#pragma unroll
            for (int k16 = 0; k16 < 4; k16++) {
                const uint32_t cb = (uint32_t)k16 * 32 + ((lane >> 4) << 4);

                // batch A frags (4 ldsm, MLP)
                uint32_t ah[2][4], al[2][4];
#pragma unroll
                for (int mt = 0; mt < 2; mt++) {
                    const int mrow = mset + mt * 16 + mrl;
                    uint32_t a = stg + AHI + (uint32_t)mrow * 128
                               + (cb ^ ((uint32_t)(mrow & 7) << 4));
                    ldsm4(ah[mt], a);
                    ldsm4(al[mt], a + (ALO - AHI));
                }
#pragma unroll
                for (int n16 = 0; n16 < 4; n16++) {
                    const int nrow = ng + n16 * 16 + nrl;
                    uint32_t b = stg + BHI + (uint32_t)nrow * 128
                               + (cb ^ ((uint32_t)(nrow & 7) << 4));
                    uint32_t bh[4], bl[4];
                    ldsm4(bh, b);
                    ldsm4(bl, b + (BLO - BHI));
                    // term-major within n16: same-acc RAW distance 4
#pragma unroll
                    for (int mt = 0; mt < 2; mt++) {
                        mma16816(acc[mt][n16 * 2 + 0], ah[mt], bh[0], bh[2]);
                        mma16816(acc[mt][n16 * 2 + 1], ah[mt], bh[1], bh[3]);
                    }
#pragma unroll
                    for (int mt = 0; mt < 2; mt++) {
                        mma16816(acc[mt][n16 * 2 + 0], ah[mt], bl[0], bl[2]);
                        mma16816(acc[mt][n16 * 2 + 1], ah[mt], bl[1], bl[3]);
                    }
#pragma unroll
                    for (int mt = 0; mt < 2; mt++) {
                        mma16816(acc[mt][n16 * 2 + 0], al[mt], bh[0], bh[2]);
                        mma16816(acc[mt][n16 * 2 + 1], al[mt], bh[1], bh[3]);
                    }
                }
            }
            mbar_arrive(sb + 24 + s * 8);
            if (++s == NSTAGE) s = 0;
        }

        // epilogue: write logits straight from registers
        const int cl0 = 2 * (lane & 3);
#pragma unroll
        for (int mt = 0; mt < 2; mt++) {
            const int m0 = mset + mt * 16 + (lane >> 2);
#pragma unroll
            for (int nf = 0; nf < 8; nf++) {
                const int col = bn + ng + nf * 8 + cl0;
                *(float2*)&out_logits[(size_t)(bm + m0) * N_EXPERTS + col] =
                    make_float2(acc[mt][nf][0], acc[mt][nf][1]);
                *(float2*)&out_logits[(size_t)(bm + m0 + 8) * N_EXPERTS + col] =
                    make_float2(acc[mt][nf][2], acc[mt][nf][3]);
            }
        }
    } else {
        // ============ PRODUCER ============
        const int pt = tid - 256;                 // 0..255
        const int arow = pt >> 1;                 // 0..127
        const int acol = (pt & 1) * 32;           // 32 floats each
        const uint32_t axor = (uint32_t)(arow & 7) << 4;
        const float* hp = H + (size_t)(bm + arow) * D_MODEL + acol;
        const int brow  = pt >> 1;                // 0..127
        const int bhalf = (pt & 1) * 32;          // bf16 col offset
        const uint32_t bxor = (uint32_t)(brow & 7) << 4;
        const __nv_bfloat16* whp = g_whi + (size_t)(bn + brow) * D_MODEL + bhalf;
        const __nv_bfloat16* wlp = g_wlo + (size_t)(bn + brow) * D_MODEL + bhalf;
        int ph[NSTAGE] = {0, 0, 0};
        int s = 0;

        float4 ha[8];
#pragma unroll
        for (int j = 0; j < 8; j++) ha[j] = *(const float4*)(hp + j * 4);

        for (int c = 0; c < NCHUNK; c++) {
            if (c >= NSTAGE) { mbar_wait(sb + 24 + s * 8, ph[s]); ph[s] ^= 1; }
            char* stage = smem + STAGE_OFF + s * STAGE_BYTES;
            const uint32_t stg = sb + STAGE_OFF + s * STAGE_BYTES;

            // A convert + STS (32 floats)
#pragma unroll
            for (int j = 0; j < 8; j++) {
                uint32_t off = (uint32_t)arow * 128
                             + (((uint32_t)(acol + j * 4) * 2) ^ axor);
                uint2 hi, lo;
                pack_hilo(ha[j].x, ha[j].y, hi.x, lo.x);
                pack_hilo(ha[j].z, ha[j].w, hi.y, lo.y);
                *(uint2*)(stage + AHI + off) = hi;
                *(uint2*)(stage + ALO + off) = lo;
            }
            mbar_arrive(sb + s * 8);

            // B via cp.async (pre-split bf16): 64B hi + 64B lo per thread
            const uint32_t bd = stg + BHI + (uint32_t)brow * 128;
#pragma unroll
            for (int j = 0; j < 4; j++) {
                uint32_t sw = (((uint32_t)(bhalf + j * 8) * 2) ^ bxor);
                cp16(bd + sw, whp + c * BK + j * 8);
                cp16(bd + (BLO - BHI) + sw, wlp + c * BK + j * 8);
            }
            cpasync_mbar_arrive(sb + s * 8);

            // prefetch next A while cp.asyncs fly
            if (c + 1 < NCHUNK) {
                const float* hn = hp + (c + 1) * BK;
#pragma unroll
                for (int j = 0; j < 8; j++) ha[j] = *(const float4*)(hn + j * 4);
            }
            if (++s == NSTAGE) s = 0;
        }
    }
}

// ---- kernel 2: topk (one warp per token) ----
__global__ __launch_bounds__(256) void moe_topk_kernel(
    const float* __restrict__ logits,
    float* __restrict__ out_idx,
    float* __restrict__ out_w)
{
    __shared__ float sc[8][N_EXPERTS];
    __shared__ float bval[8][TOPK_TOTAL];
    __shared__ int   bidx[8][TOPK_TOTAL];

    const int warp = threadIdx.x >> 5;
    const int lane = threadIdx.x & 31;
    const int t = blockIdx.x * 8 + warp;

    const float* lg = logits + (size_t)t * N_EXPERTS;
#pragma unroll
    for (int i = 0; i < N_EXPERTS / 32; i++) {
        float x = lg[lane + i * 32];
        sc[warp][lane + i * 32] = 1.f / (1.f + __expf(-x));
    }
    __syncwarp();

    if (lane < N_GROUP) {
        const int g = lane;
        float b1 = -1.f, b2 = -1.f;
        int i1 = 0, i2 = 0;
#pragma unroll 4
        for (int j = 0; j < GROUP_SIZE; j++) {
            float s = sc[warp][g * GROUP_SIZE + j];
            if (s > b1) { b2 = b1; i2 = i1; b1 = s; i1 = j; }
            else if (s > b2) { b2 = s; i2 = j; }
        }
        bval[warp][g * 2]     = b1; bidx[warp][g * 2]     = g * GROUP_SIZE + i1;
        bval[warp][g * 2 + 1] = b2; bidx[warp][g * 2 + 1] = g * GROUP_SIZE + i2;
    }
    __syncwarp();

    if (lane == 0) {
        float sum = 0.f;
#pragma unroll
        for (int j = 0; j < TOPK_TOTAL; j++) sum += bval[warp][j];
        float scale = 2.5f / (sum + 1e-10f);
#pragma unroll
        for (int j = 0; j < TOPK_TOTAL; j++) {
            out_idx[(size_t)t * TOPK_TOTAL + j] = (float)bidx[warp][j];
            out_w[(size_t)t * TOPK_TOTAL + j]   = bval[warp][j] * scale;
        }
    }
}

extern "C" void kernel_launch(void* const* d_in, const int* in_sizes, int n_in,
                              void* d_out, int out_size)
{
    const float* H = (const float*)d_in[0];   // [8192, 4096]
    const float* W = (const float*)d_in[1];   // [256, 4096]
    float* out = (float*)d_out;

    float* out_idx    = out;
    float* out_w      = out + (size_t)N_TOKENS * TOPK_TOTAL;
    float* out_logits = out + (size_t)N_TOKENS * TOPK_TOTAL * 2;

    static int configured = 0;
    if (!configured) {
        cudaFuncSetAttribute(moe_gemm_kernel,
                             cudaFuncAttributeMaxDynamicSharedMemorySize, SMEM_TOTAL);
        configured = 1;
    }
    split_w_kernel<<<(N_EXPERTS * D_MODEL / 4) / 256, 256>>>(W);
    moe_gemm_kernel<<<(N_TOKENS / BM) * (N_EXPERTS / BN), THREADS, SMEM_TOTAL>>>(H, out_logits);
    moe_topk_kernel<<<N_TOKENS / 8, 256>>>(out_logits, out_idx, out_w);
}

// round 15
// speedup vs baseline: 1.4769x; 1.0528x over previous
#include <cuda_runtime.h>
#include <cuda_bf16.h>
#include <cstdint>

#define N_TOKENS 8192
#define D_MODEL  4096
#define N_EXPERTS 256
#define N_GROUP 4
#define GROUP_SIZE 64
#define TOPK_TOTAL 8

#define BM 128
#define BN 128
#define BK 64
#define NCHUNK (D_MODEL / BK)   // 64
#define THREADS 768             // 16 consumer + 8 producer warps
#define NSTAGE 3

// stage layout (bytes): Ahi[128*128] Alo Bhi[128*128] Blo
#define AHI 0
#define ALO 16384
#define BHI 32768
#define BLO 49152
#define STAGE_BYTES 65536
#define STAGE_OFF 1024
#define SMEM_TOTAL (STAGE_OFF + NSTAGE * STAGE_BYTES)   // 197632

// pre-split W (bf16 hi/lo)
__device__ __nv_bfloat16 g_whi[N_EXPERTS * D_MODEL];
__device__ __nv_bfloat16 g_wlo[N_EXPERTS * D_MODEL];

__device__ __forceinline__ uint32_t smem_u32(const void* p) {
    uint32_t a;
    asm("{ .reg .u64 t; cvta.to.shared.u64 t, %1; cvt.u32.u64 %0, t; }" : "=r"(a) : "l"(p));
    return a;
}
__device__ __forceinline__ void mbar_init(uint32_t m, uint32_t cnt) {
    asm volatile("mbarrier.init.shared.b64 [%0], %1;" :: "r"(m), "r"(cnt) : "memory");
}
__device__ __forceinline__ void mbar_wait(uint32_t m, int parity) {
    asm volatile(
        "{\n\t.reg .pred P;\n\t"
        "WL_%=:\n\t"
        "mbarrier.try_wait.parity.acquire.cta.shared::cta.b64 P, [%0], %1;\n\t"
        "@!P bra WL_%=;\n\t}"
        :: "r"(m), "r"(parity) : "memory");
}
__device__ __forceinline__ void mbar_arrive(uint32_t m) {
    asm volatile("mbarrier.arrive.shared.b64 _, [%0];" :: "r"(m) : "memory");
}
__device__ __forceinline__ void cpasync_mbar_arrive(uint32_t m) {
    asm volatile("cp.async.mbarrier.arrive.noinc.shared.b64 [%0];" :: "r"(m) : "memory");
}
__device__ __forceinline__ void cp16(uint32_t dst, const void* src) {
    asm volatile("cp.async.cg.shared.global [%0], [%1], 16;" :: "r"(dst), "l"(src) : "memory");
}
__device__ __forceinline__ void ldsm4(uint32_t (&r)[4], uint32_t addr) {
    asm volatile("ldmatrix.sync.aligned.m8n8.x4.shared.b16 {%0,%1,%2,%3}, [%4];"
                 : "=r"(r[0]), "=r"(r[1]), "=r"(r[2]), "=r"(r[3]) : "r"(addr));
}
__device__ __forceinline__ void mma16816(float (&c)[4], const uint32_t (&a)[4],
                                         uint32_t b0, uint32_t b1) {
    asm volatile("mma.sync.aligned.m16n8k16.row.col.f32.bf16.bf16.f32 "
                 "{%0,%1,%2,%3}, {%4,%5,%6,%7}, {%8,%9}, {%0,%1,%2,%3};"
                 : "+f"(c[0]), "+f"(c[1]), "+f"(c[2]), "+f"(c[3])
                 : "r"(a[0]), "r"(a[1]), "r"(a[2]), "r"(a[3]), "r"(b0), "r"(b1));
}
__device__ __forceinline__ void pack_hilo(float x, float y, uint32_t& hi, uint32_t& lo) {
    asm("cvt.rn.bf16x2.f32 %0, %1, %2;" : "=r"(hi) : "f"(y), "f"(x));
    float hx = __uint_as_float(hi << 16);
    float hy = __uint_as_float(hi & 0xFFFF0000u);
    asm("cvt.rn.bf16x2.f32 %0, %1, %2;" : "=r"(lo) : "f"(y - hy), "f"(x - hx));
}

// ---- kernel 0: split W fp32 -> bf16 hi/lo ----
__global__ __launch_bounds__(256) void split_w_kernel(const float* __restrict__ W) {
    size_t i = ((size_t)blockIdx.x * 256 + threadIdx.x) * 4;
    float4 v = *(const float4*)(W + i);
    uint2 hi, lo;
    pack_hilo(v.x, v.y, hi.x, lo.x);
    pack_hilo(v.z, v.w, hi.y, lo.y);
    *(uint2*)(g_whi + i) = hi;
    *(uint2*)(g_wlo + i) = lo;
}

// ---- kernel 1: warp-specialized GEMM, 32x32 consumer tiles, 16C+8P warps ----
__global__ __launch_bounds__(THREADS, 1) void moe_gemm_kernel(
    const float* __restrict__ H,
    float* __restrict__ out_logits)
{
    extern __shared__ char smem[];
    const uint32_t sb = smem_u32(smem);
    const int tid  = threadIdx.x;
    const int wid  = tid >> 5;
    const int lane = tid & 31;
    const int bm   = (blockIdx.x >> 1) * BM;
    const int bn   = (blockIdx.x & 1) * BN;

    // full[s] at sb+s*8 (count 512: 256 producer STS + 256 cp.async arrives)
    // empty[s] at sb+24+s*8 (count 512: consumer threads)
    if (tid == 0) {
#pragma unroll
        for (int s = 0; s < NSTAGE; s++) {
            mbar_init(sb + s * 8, 512);
            mbar_init(sb + 24 + s * 8, 512);
        }
    }
    __syncthreads();

    if (wid < 16) {
        // ============ CONSUMER: warp tile 32 x 32 ============
        const int mset = (wid & 3) * 32;
        const int ng   = (wid >> 2) * 32;
        int ph[NSTAGE] = {0, 0, 0};
        int s = 0;

        float acc[2][4][4];
#pragma unroll
        for (int a = 0; a < 2; a++)
#pragma unroll
            for (int b = 0; b < 4; b++)
#pragma unroll
                for (int c = 0; c < 4; c++) acc[a][b][c] = 0.f;

        const int mrl = lane & 15;
        const int nrl = lane & 15;

        for (int c = 0; c < NCHUNK; c++) {
            mbar_wait(sb + s * 8, ph[s]); ph[s] ^= 1;
            const uint32_t stg = sb + STAGE_OFF + s * STAGE_BYTES;
#pragma unroll
            for (int k16 = 0; k16 < 4; k16++) {
                const uint32_t cb = (uint32_t)k16 * 32 + ((lane >> 4) << 4);

                // batch A frags (4 ldsm)
                uint32_t ah[2][4], al[2][4];
#pragma unroll
                for (int mt = 0; mt < 2; mt++) {
                    const int mrow = mset + mt * 16 + mrl;
                    uint32_t a = stg + AHI + (uint32_t)mrow * 128
                               + (cb ^ ((uint32_t)(mrow & 7) << 4));
                    ldsm4(ah[mt], a);
                    ldsm4(al[mt], a + (ALO - AHI));
                }
#pragma unroll
                for (int n16 = 0; n16 < 2; n16++) {
                    const int nrow = ng + n16 * 16 + nrl;
                    uint32_t b = stg + BHI + (uint32_t)nrow * 128
                               + (cb ^ ((uint32_t)(nrow & 7) << 4));
                    uint32_t bh[4], bl[4];
                    ldsm4(bh, b);
                    ldsm4(bl, b + (BLO - BHI));
#pragma unroll
                    for (int mt = 0; mt < 2; mt++) {
                        mma16816(acc[mt][n16 * 2 + 0], ah[mt], bh[0], bh[2]);
                        mma16816(acc[mt][n16 * 2 + 1], ah[mt], bh[1], bh[3]);
                    }
#pragma unroll
                    for (int mt = 0; mt < 2; mt++) {
                        mma16816(acc[mt][n16 * 2 + 0], ah[mt], bl[0], bl[2]);
                        mma16816(acc[mt][n16 * 2 + 1], ah[mt], bl[1], bl[3]);
                    }
#pragma unroll
                    for (int mt = 0; mt < 2; mt++) {
                        mma16816(acc[mt][n16 * 2 + 0], al[mt], bh[0], bh[2]);
                        mma16816(acc[mt][n16 * 2 + 1], al[mt], bh[1], bh[3]);
                    }
                }
            }
            mbar_arrive(sb + 24 + s * 8);
            if (++s == NSTAGE) s = 0;
        }

        // epilogue: write logits straight from registers
        const int cl0 = 2 * (lane & 3);
#pragma unroll
        for (int mt = 0; mt < 2; mt++) {
            const int m0 = mset + mt * 16 + (lane >> 2);
#pragma unroll
            for (int nf = 0; nf < 4; nf++) {
                const int col = bn + ng + nf * 8 + cl0;
                *(float2*)&out_logits[(size_t)(bm + m0) * N_EXPERTS + col] =
                    make_float2(acc[mt][nf][0], acc[mt][nf][1]);
                *(float2*)&out_logits[(size_t)(bm + m0 + 8) * N_EXPERTS + col] =
                    make_float2(acc[mt][nf][2], acc[mt][nf][3]);
            }
        }
    } else {
        // ============ PRODUCER (8 warps, 256 threads) ============
        const int pt = tid - 512;                 // 0..255
        const int arow = pt >> 1;                 // 0..127
        const int acol = (pt & 1) * 32;           // 32 floats each
        const uint32_t axor = (uint32_t)(arow & 7) << 4;
        const float* hp = H + (size_t)(bm + arow) * D_MODEL + acol;
        const int brow  = pt >> 1;                // 0..127
        const int bhalf = (pt & 1) * 32;          // bf16 col offset
        const uint32_t bxor = (uint32_t)(brow & 7) << 4;
        const __nv_bfloat16* whp = g_whi + (size_t)(bn + brow) * D_MODEL + bhalf;
        const __nv_bfloat16* wlp = g_wlo + (size_t)(bn + brow) * D_MODEL + bhalf;
        int ph[NSTAGE] = {0, 0, 0};
        int s = 0;

        float4 ha[8];
#pragma unroll
        for (int j = 0; j < 8; j++) ha[j] = *(const float4*)(hp + j * 4);

        for (int c = 0; c < NCHUNK; c++) {
            if (c >= NSTAGE) { mbar_wait(sb + 24 + s * 8, ph[s]); ph[s] ^= 1; }
            char* stage = smem + STAGE_OFF + s * STAGE_BYTES;
            const uint32_t stg = sb + STAGE_OFF + s * STAGE_BYTES;

            // A convert + STS (32 floats)
#pragma unroll
            for (int j = 0; j < 8; j++) {
                uint32_t off = (uint32_t)arow * 128
                             + (((uint32_t)(acol + j * 4) * 2) ^ axor);
                uint2 hi, lo;
                pack_hilo(ha[j].x, ha[j].y, hi.x, lo.x);
                pack_hilo(ha[j].z, ha[j].w, hi.y, lo.y);
                *(uint2*)(stage + AHI + off) = hi;
                *(uint2*)(stage + ALO + off) = lo;
            }
            mbar_arrive(sb + s * 8);

            // B via cp.async (pre-split bf16): 64B hi + 64B lo per thread
            const uint32_t bd = stg + BHI + (uint32_t)brow * 128;
#pragma unroll
            for (int j = 0; j < 4; j++) {
                uint32_t sw = (((uint32_t)(bhalf + j * 8) * 2) ^ bxor);
                cp16(bd + sw, whp + c * BK + j * 8);
                cp16(bd + (BLO - BHI) + sw, wlp + c * BK + j * 8);
            }
            cpasync_mbar_arrive(sb + s * 8);

            // prefetch next A while cp.asyncs fly
            if (c + 1 < NCHUNK) {
                const float* hn = hp + (c + 1) * BK;
#pragma unroll
                for (int j = 0; j < 8; j++) ha[j] = *(const float4*)(hn + j * 4);
            }
            if (++s == NSTAGE) s = 0;
        }
    }
}

// ---- kernel 2: topk (one warp per token) ----
__global__ __launch_bounds__(256) void moe_topk_kernel(
    const float* __restrict__ logits,
    float* __restrict__ out_idx,
    float* __restrict__ out_w)
{
    __shared__ float sc[8][N_EXPERTS];
    __shared__ float bval[8][TOPK_TOTAL];
    __shared__ int   bidx[8][TOPK_TOTAL];

    const int warp = threadIdx.x >> 5;
    const int lane = threadIdx.x & 31;
    const int t = blockIdx.x * 8 + warp;

    const float* lg = logits + (size_t)t * N_EXPERTS;
#pragma unroll
    for (int i = 0; i < N_EXPERTS / 32; i++) {
        float x = lg[lane + i * 32];
        sc[warp][lane + i * 32] = 1.f / (1.f + __expf(-x));
    }
    __syncwarp();

    if (lane < N_GROUP) {
        const int g = lane;
        float b1 = -1.f, b2 = -1.f;
        int i1 = 0, i2 = 0;
#pragma unroll 4
        for (int j = 0; j < GROUP_SIZE; j++) {
            float s = sc[warp][g * GROUP_SIZE + j];
            if (s > b1) { b2 = b1; i2 = i1; b1 = s; i1 = j; }
            else if (s > b2) { b2 = s; i2 = j; }
        }
        bval[warp][g * 2]     = b1; bidx[warp][g * 2]     = g * GROUP_SIZE + i1;
        bval[warp][g * 2 + 1] = b2; bidx[warp][g * 2 + 1] = g * GROUP_SIZE + i2;
    }
    __syncwarp();

    if (lane == 0) {
        float sum = 0.f;
#pragma unroll
        for (int j = 0; j < TOPK_TOTAL; j++) sum += bval[warp][j];
        float scale = 2.5f / (sum + 1e-10f);
#pragma unroll
        for (int j = 0; j < TOPK_TOTAL; j++) {
            out_idx[(size_t)t * TOPK_TOTAL + j] = (float)bidx[warp][j];
            out_w[(size_t)t * TOPK_TOTAL + j]   = bval[warp][j] * scale;
        }
    }
}

extern "C" void kernel_launch(void* const* d_in, const int* in_sizes, int n_in,
                              void* d_out, int out_size)
{
    const float* H = (const float*)d_in[0];   // [8192, 4096]
    const float* W = (const float*)d_in[1];   // [256, 4096]
    float* out = (float*)d_out;

    float* out_idx    = out;
    float* out_w      = out + (size_t)N_TOKENS * TOPK_TOTAL;
    float* out_logits = out + (size_t)N_TOKENS * TOPK_TOTAL * 2;

    static int configured = 0;
    if (!configured) {
        cudaFuncSetAttribute(moe_gemm_kernel,
                             cudaFuncAttributeMaxDynamicSharedMemorySize, SMEM_TOTAL);
        configured = 1;
    }
    split_w_kernel<<<(N_EXPERTS * D_MODEL / 4) / 256, 256>>>(W);
    moe_gemm_kernel<<<(N_TOKENS / BM) * (N_EXPERTS / BN), THREADS, SMEM_TOTAL>>>(H, out_logits);
    moe_topk_kernel<<<N_TOKENS / 8, 256>>>(out_logits, out_idx, out_w);
}